// round 1
// baseline (speedup 1.0000x reference)
#include <cuda_runtime.h>
#include <cstdint>

#define THREADS 128
#define BPB 2                 // batches per block
#define FS 32                 // F_SIZE
#define DIM 64
#define XROW 72               // padded smem row (conflict-free d-access)
#define WPAD 33               // padded W smem row (conflict-free o-access)
#define WSTAGE (128 * WPAD)   // floats per W stage buffer

typedef unsigned long long u64t;

static __device__ __forceinline__ u64t fma2(u64t a, u64t b, u64t c) {
    u64t d; asm("fma.rn.f32x2 %0, %1, %2, %3;" : "=l"(d) : "l"(a), "l"(b), "l"(c)); return d;
}
static __device__ __forceinline__ u64t mul2(u64t a, u64t b) {
    u64t d; asm("mul.rn.f32x2 %0, %1, %2;" : "=l"(d) : "l"(a), "l"(b)); return d;
}
static __device__ __forceinline__ u64t dup2(float w) {
    u64t d; unsigned r = __float_as_uint(w);
    asm("mov.b64 %0, {%1, %1};" : "=l"(d) : "r"(r)); return d;
}
static __device__ __forceinline__ void unpack2(u64t v, float& lo, float& hi) {
    unsigned a, b; asm("mov.b64 {%0, %1}, %2;" : "=r"(a), "=r"(b) : "l"(v));
    lo = __uint_as_float(a); hi = __uint_as_float(b);
}
static __device__ __forceinline__ void cpa4(uint32_t s, const float* g) {
    asm volatile("cp.async.ca.shared.global [%0], [%1], 4;" :: "r"(s), "l"(g));
}
static __device__ __forceinline__ void cp_commit() { asm volatile("cp.async.commit_group;"); }
template <int N>
static __device__ __forceinline__ void cp_wait() { asm volatile("cp.async.wait_group %0;" :: "n"(N)); }

// One CIN layer: acc[b][i][j-pair] += sum over k=(h*32+m) of W[o0+i][k] * xh[h,d]*xm[m,d]
// W staged per-h (32 k's) through a cp.async double buffer.
template <int NH>
static __device__ __forceinline__ void run_layer(
    const float* __restrict__ Wg, const int K,
    const float* xh0p, const float* xh1p,   // per-batch h source (xs or hs)
    const float* xm0p, const float* xm1p,   // per-batch m source (always xs)
    const float* wsmem, uint32_t ws_s,
    int t, int o0, int xoff, u64t acc[BPB][8][4])
{
    const int mlane = t & 31;
    const int obase = t >> 5;
    int buf = 0;

    // issue stage h=0 into buf 0
    {
        const float* g = Wg + mlane;
        uint32_t sbase = ws_s + (uint32_t)(obase * WPAD + mlane) * 4u;
        #pragma unroll
        for (int i = 0; i < 32; i++)
            cpa4(sbase + (uint32_t)(i * 4 * WPAD) * 4u, g + (size_t)(obase + i * 4) * K);
        cp_commit();
    }

    for (int h = 0; h < NH; ++h) {
        if (h + 1 < NH) {
            const float* g = Wg + (h + 1) * FS + mlane;
            uint32_t sbase = ws_s + (uint32_t)((1 - buf) * WSTAGE + obase * WPAD + mlane) * 4u;
            #pragma unroll
            for (int i = 0; i < 32; i++)
                cpa4(sbase + (uint32_t)(i * 4 * WPAD) * 4u, g + (size_t)(obase + i * 4) * K);
            cp_commit();
            cp_wait<1>();
        } else {
            cp_wait<0>();
        }
        __syncthreads();

        // xh for this h, both batches (4 f32x2 pairs each = 8 d's)
        u64t xh[BPB][4];
        {
            const float* p = xh0p + h * XROW + xoff;
            ulonglong2 a = *(const ulonglong2*)p;
            ulonglong2 c = *(const ulonglong2*)(p + 4);
            xh[0][0] = a.x; xh[0][1] = a.y; xh[0][2] = c.x; xh[0][3] = c.y;
            p = xh1p + h * XROW + xoff;
            a = *(const ulonglong2*)p; c = *(const ulonglong2*)(p + 4);
            xh[1][0] = a.x; xh[1][1] = a.y; xh[1][2] = c.x; xh[1][3] = c.y;
        }

        const float* wsb = wsmem + buf * WSTAGE + o0 * WPAD;
        #pragma unroll 4
        for (int m = 0; m < FS; m++) {
            u64t w2[8];
            #pragma unroll
            for (int i = 0; i < 8; i++) w2[i] = dup2(wsb[i * WPAD + m]);
            #pragma unroll
            for (int b = 0; b < BPB; b++) {
                const float* xmp = (b ? xm1p : xm0p) + m * XROW + xoff;
                ulonglong2 A  = *(const ulonglong2*)xmp;
                ulonglong2 Bv = *(const ulonglong2*)(xmp + 4);
                u64t z0 = mul2(xh[b][0], A.x);
                u64t z1 = mul2(xh[b][1], A.y);
                u64t z2 = mul2(xh[b][2], Bv.x);
                u64t z3 = mul2(xh[b][3], Bv.y);
                #pragma unroll
                for (int i = 0; i < 8; i++) {
                    acc[b][i][0] = fma2(w2[i], z0, acc[b][i][0]);
                    acc[b][i][1] = fma2(w2[i], z1, acc[b][i][1]);
                    acc[b][i][2] = fma2(w2[i], z2, acc[b][i][2]);
                    acc[b][i][3] = fma2(w2[i], z3, acc[b][i][3]);
                }
            }
        }
        __syncthreads();
        buf ^= 1;
    }
}

__global__ __launch_bounds__(THREADS, 2)
void cin_kernel(const float* __restrict__ xg,
                const float* __restrict__ W0, const float* __restrict__ b0g,
                const float* __restrict__ W1, const float* __restrict__ b1g,
                float* __restrict__ out)
{
    extern __shared__ float sm[];
    float* xs = sm;                          // 2 * 32 * 72
    float* hs = sm + BPB * FS * XROW;        // 2 * 64 * 72
    float* ws = hs + BPB * 64 * XROW;        // 2 * WSTAGE
    uint32_t ws_s = (uint32_t)__cvta_generic_to_shared(ws);

    const int t  = threadIdx.x;
    const int og = t >> 3, dg = t & 7;
    const int o0 = og * 8, d0 = dg * 8;
    const int xoff = d0 + ((d0 >> 5) << 2);  // swizzled d offset (constant per thread)
    const int bbase = blockIdx.x * BPB;

    // Load x for both batches into swizzled smem
    #pragma unroll
    for (int b = 0; b < BPB; b++) {
        const float4* g = (const float4*)(xg + (size_t)(bbase + b) * FS * DIM);
        float* xsb = xs + b * FS * XROW;
        #pragma unroll
        for (int i = 0; i < 4; i++) {
            int idx4 = i * THREADS + t;
            int h = idx4 >> 4;
            int d = (idx4 & 15) << 2;
            *(float4*)(xsb + h * XROW + d + ((d >> 5) << 2)) = g[idx4];
        }
    }
    __syncthreads();

    u64t acc[BPB][8][4];
    #pragma unroll
    for (int b = 0; b < BPB; b++)
        #pragma unroll
        for (int i = 0; i < 8; i++)
            #pragma unroll
            for (int j = 0; j < 4; j++) acc[b][i][j] = 0ull;

    // ---- Layer 0: K = 1024, h-source = x ----
    run_layer<FS>(W0, FS * FS,
                  xs, xs + FS * XROW, xs, xs + FS * XROW,
                  ws, ws_s, t, o0, xoff, acc);

    // Epilogue 0: bias+relu; o<64 -> hs (next layer input); o>=64 -> result rows 0..63
    float bias0[8];
    #pragma unroll
    for (int i = 0; i < 8; i++) bias0[i] = b0g[o0 + i];

    #pragma unroll
    for (int b = 0; b < BPB; b++) {
        float* hsb = hs + b * 64 * XROW;
        float p[8];
        #pragma unroll
        for (int i = 0; i < 8; i++) {
            float v[8];
            unpack2(acc[b][i][0], v[0], v[1]);
            unpack2(acc[b][i][1], v[2], v[3]);
            unpack2(acc[b][i][2], v[4], v[5]);
            unpack2(acc[b][i][3], v[6], v[7]);
            #pragma unroll
            for (int j = 0; j < 8; j++) v[j] = fmaxf(v[j] + bias0[i], 0.0f);
            if (o0 < 64) {
                float* dst = hsb + (o0 + i) * XROW + xoff;
                *(float4*)dst       = make_float4(v[0], v[1], v[2], v[3]);
                *(float4*)(dst + 4) = make_float4(v[4], v[5], v[6], v[7]);
            } else {
                p[i] = ((v[0] + v[1]) + (v[2] + v[3])) + ((v[4] + v[5]) + (v[6] + v[7]));
            }
        }
        if (o0 >= 64) {   // warp-uniform branch
            #pragma unroll
            for (int i = 0; i < 8; i++) {
                p[i] += __shfl_xor_sync(0xffffffffu, p[i], 1);
                p[i] += __shfl_xor_sync(0xffffffffu, p[i], 2);
                p[i] += __shfl_xor_sync(0xffffffffu, p[i], 4);
            }
            #pragma unroll
            for (int i = 0; i < 8; i++)
                if (dg == i) out[(size_t)(bbase + b) * 192 + (o0 - 64) + i] = p[i];
        }
    }
    __syncthreads();   // hs complete before layer 1 reads it

    #pragma unroll
    for (int b = 0; b < BPB; b++)
        #pragma unroll
        for (int i = 0; i < 8; i++)
            #pragma unroll
            for (int j = 0; j < 4; j++) acc[b][i][j] = 0ull;

    // ---- Layer 1: K = 2048, h-source = hs (64 rows) ----
    run_layer<64>(W1, 64 * FS,
                  hs, hs + 64 * XROW, xs, xs + FS * XROW,
                  ws, ws_s, t, o0, xoff, acc);

    // Epilogue 1: bias+relu; all 128 o -> result rows 64..191
    float bias1[8];
    #pragma unroll
    for (int i = 0; i < 8; i++) bias1[i] = b1g[o0 + i];

    #pragma unroll
    for (int b = 0; b < BPB; b++) {
        float p[8];
        #pragma unroll
        for (int i = 0; i < 8; i++) {
            float v[8];
            unpack2(acc[b][i][0], v[0], v[1]);
            unpack2(acc[b][i][1], v[2], v[3]);
            unpack2(acc[b][i][2], v[4], v[5]);
            unpack2(acc[b][i][3], v[6], v[7]);
            float s = 0.0f;
            #pragma unroll
            for (int j = 0; j < 8; j++) s += fmaxf(v[j] + bias1[i], 0.0f);
            p[i] = s;
        }
        #pragma unroll
        for (int i = 0; i < 8; i++) {
            p[i] += __shfl_xor_sync(0xffffffffu, p[i], 1);
            p[i] += __shfl_xor_sync(0xffffffffu, p[i], 2);
            p[i] += __shfl_xor_sync(0xffffffffu, p[i], 4);
        }
        #pragma unroll
        for (int i = 0; i < 8; i++)
            if (dg == i) out[(size_t)(bbase + b) * 192 + 64 + o0 + i] = p[i];
    }
}

extern "C" void kernel_launch(void* const* d_in, const int* in_sizes, int n_in,
                              void* d_out, int out_size) {
    const float* xg = (const float*)d_in[0];   // inputs (2048,32,64)
    const float* W0 = (const float*)d_in[1];   // (128,1024)
    const float* b0 = (const float*)d_in[2];   // (128)
    const float* W1 = (const float*)d_in[3];   // (128,2048)
    const float* b1 = (const float*)d_in[4];   // (128)
    float* out = (float*)d_out;                // (2048,192)

    const int smem_bytes = (BPB * FS * XROW + BPB * 64 * XROW + 2 * WSTAGE) * 4; // 89088
    cudaFuncSetAttribute((const void*)cin_kernel,
                         cudaFuncAttributeMaxDynamicSharedMemorySize, smem_bytes);
    cin_kernel<<<2048 / BPB, THREADS, smem_bytes>>>(xg, W0, b0, W1, b1, out);
}

// round 4
// speedup vs baseline: 2.3389x; 2.3389x over previous
#include <cuda_runtime.h>
#include <cuda_bf16.h>
#include <cstdint>

// ---------------- configuration ----------------
#define NB      4            // batches per CTA
#define THREADS 256
#define HPAD    65           // h row pitch (floats)
#define NT0     16           // layer-0 K tiles (K=1024, 64 k per tile)
#define NT_ALL  48           // + 32 layer-1 tiles (K=2048)
#define WPITCH  144          // W/z row pitch in bytes (72 bf16)
#define WPLANE  18432        // 128 rows * 144B  (one bf16 plane of a W tile)
#define WTILE   36864        // hi+lo planes
#define ZPLANE  9216         // 64 rows * 144B
#define ZTILE   18432        // hi+lo planes

// dynamic smem byte offsets
#define OFF_X   0            // 4 * 8192   x fp32 [32][64] per batch
#define OFF_H   32768        // 4 * 16640  h fp32 [64][HPAD] per batch
#define OFF_W   99328        // 2 * WTILE
#define OFF_Z   173056       // 2 * ZTILE   (epilogue partial sums overlay here)
#define SMEM_TOTAL 209920

// pre-split W: 48 tiles, each [hi plane 128x144B][lo plane 128x144B]
__device__ __align__(16) unsigned char g_Wpre[48 * WTILE];

// ---------------- helpers ----------------
static __device__ __forceinline__ uint32_t smem_u32(const void* p) {
    return (uint32_t)__cvta_generic_to_shared(p);
}
static __device__ __forceinline__ void cpa16(uint32_t dst, const void* src) {
    asm volatile("cp.async.cg.shared.global [%0], [%1], 16;" :: "r"(dst), "l"(src));
}
static __device__ __forceinline__ void cp_commit() { asm volatile("cp.async.commit_group;"); }
template <int N>
static __device__ __forceinline__ void cp_wait() { asm volatile("cp.async.wait_group %0;" :: "n"(N)); }

// ORDERED shared load: volatile + memory clobber so it can never be hoisted
// across __syncthreads()/cp.async.wait_group (the round-3 correctness bug).
static __device__ __forceinline__ uint32_t lds32(uint32_t a) {
    uint32_t v; asm volatile("ld.shared.b32 %0, [%1];" : "=r"(v) : "r"(a) : "memory"); return v;
}
static __device__ __forceinline__ void sts128(uint32_t a, uint32_t r0, uint32_t r1, uint32_t r2, uint32_t r3) {
    asm volatile("st.shared.v4.b32 [%0], {%1, %2, %3, %4};" :: "r"(a), "r"(r0), "r"(r1), "r"(r2), "r"(r3) : "memory");
}
// m16n8k16 row.col bf16 -> f32, D += A*B  (register-pure; ordered by data deps)
static __device__ __forceinline__ void mma16816(float* c, const uint32_t* a, const uint32_t* b) {
    asm volatile(
        "mma.sync.aligned.m16n8k16.row.col.f32.bf16.bf16.f32 "
        "{%0,%1,%2,%3}, {%4,%5,%6,%7}, {%8,%9}, {%0,%1,%2,%3};"
        : "+f"(c[0]), "+f"(c[1]), "+f"(c[2]), "+f"(c[3])
        : "r"(a[0]), "r"(a[1]), "r"(a[2]), "r"(a[3]), "r"(b[0]), "r"(b[1]));
}

// ---------------- prep: split W into bf16 hi/lo, padded-pitch tiles ----------------
__global__ void prep_kernel(const float* __restrict__ W0, const float* __restrict__ W1) {
    int idx = blockIdx.x * 256 + threadIdx.x;      // 0..393215
    float w; int o, k; size_t base;
    if (idx < 131072) { o = idx >> 10; k = idx & 1023; w = W0[idx]; base = (size_t)(k >> 6) * WTILE; }
    else { int j = idx - 131072; o = j >> 11; k = j & 2047; w = W1[j]; base = 16 * WTILE + (size_t)(k >> 6) * WTILE; }
    __nv_bfloat16 hi = __float2bfloat16(w);
    __nv_bfloat16 lo = __float2bfloat16(w - __bfloat162float(hi));
    int c = k & 63;
    size_t off = base + (size_t)o * WPITCH + (size_t)c * 2;
    *(__nv_bfloat16*)(g_Wpre + off)          = hi;
    *(__nv_bfloat16*)(g_Wpre + off + WPLANE) = lo;
}

// ---------------- main kernel ----------------
__global__ __launch_bounds__(THREADS, 1)
void cin_mma_kernel(const float* __restrict__ xg,
                    const float* __restrict__ b0g,
                    const float* __restrict__ b1g,
                    float* __restrict__ out)
{
    extern __shared__ __align__(256) unsigned char smem[];
    const uint32_t sb = smem_u32(smem);
    const int tid  = threadIdx.x;
    const int wid  = tid >> 5;
    const int lane = tid & 31;
    const int lr   = lane >> 2;     // fragment row within 8
    const int lc   = lane & 3;      // fragment col group

    const int wo = wid >> 1;        // warp o-tile (0..3) -> o base wo*32
    const int wn = wid & 1;         // warp n-tile (0..1) -> d base wn*32

    float* xs = (float*)(smem + OFF_X);
    float* hs = (float*)(smem + OFF_H);

    const int bbase = blockIdx.x * NB;

    // initial loads: x (32KB) + W tile 0, one cp.async group
    {
        const char* src = (const char*)(xg + (size_t)bbase * 2048);
        #pragma unroll
        for (int r = 0; r < 8; r++)
            cpa16(sb + OFF_X + (uint32_t)(r * THREADS + tid) * 16, src + (size_t)(r * THREADS + tid) * 16);
        #pragma unroll
        for (int r = 0; r < 9; r++) {
            int idx = r * THREADS + tid;
            if (idx < WTILE / 16)
                cpa16(sb + OFF_W + (uint32_t)idx * 16, g_Wpre + (size_t)idx * 16);
        }
        cp_commit();
    }

    // z producer mapping
    const int d  = tid & 63;
    const int kq = tid >> 6;        // 0..3 -> 16-k strip
    const int kb = kq * 16;
    const int m0 = (kq & 1) * 16;

    float acc[NB][2][4][4];
    #pragma unroll
    for (int b = 0; b < NB; b++)
        #pragma unroll
        for (int mi = 0; mi < 2; mi++)
            #pragma unroll
            for (int nj = 0; nj < 4; nj++)
                #pragma unroll
                for (int q = 0; q < 4; q++) acc[b][mi][nj][q] = 0.0f;

    for (int g = 0; g < NT_ALL; g++) {
        if (g == NT0) {
            // ======== layer-0 epilogue ========
            __syncthreads();
            float* ps = (float*)(smem + OFF_Z);   // [wn][b][row<64] partial sums
            #pragma unroll
            for (int b = 0; b < NB; b++) {
                #pragma unroll
                for (int mi = 0; mi < 2; mi++) {
                    int o  = wo * 32 + mi * 16 + lr;   // rows o, o+8
                    float bias0 = b0g[o], bias1 = b0g[o + 8];
                    if (wo < 2) {
                        float* h0 = hs + (size_t)b * (64 * HPAD) + o * HPAD;
                        float* h1 = h0 + 8 * HPAD;
                        #pragma unroll
                        for (int nj = 0; nj < 4; nj++) {
                            int dd = wn * 32 + nj * 8 + 2 * lc;
                            h0[dd]     = fmaxf(acc[b][mi][nj][0] + bias0, 0.0f);
                            h0[dd + 1] = fmaxf(acc[b][mi][nj][1] + bias0, 0.0f);
                            h1[dd]     = fmaxf(acc[b][mi][nj][2] + bias1, 0.0f);
                            h1[dd + 1] = fmaxf(acc[b][mi][nj][3] + bias1, 0.0f);
                        }
                    } else {
                        float s0 = 0.0f, s1 = 0.0f;
                        #pragma unroll
                        for (int nj = 0; nj < 4; nj++) {
                            s0 += fmaxf(acc[b][mi][nj][0] + bias0, 0.0f)
                                + fmaxf(acc[b][mi][nj][1] + bias0, 0.0f);
                            s1 += fmaxf(acc[b][mi][nj][2] + bias1, 0.0f)
                                + fmaxf(acc[b][mi][nj][3] + bias1, 0.0f);
                        }
                        s0 += __shfl_xor_sync(0xffffffffu, s0, 1);
                        s0 += __shfl_xor_sync(0xffffffffu, s0, 2);
                        s1 += __shfl_xor_sync(0xffffffffu, s1, 1);
                        s1 += __shfl_xor_sync(0xffffffffu, s1, 2);
                        if (lc == 0) {
                            int row = (wo - 2) * 32 + mi * 16 + lr;
                            ps[wn * 256 + b * 64 + row]     = s0;
                            ps[wn * 256 + b * 64 + row + 8] = s1;
                        }
                    }
                }
            }
            __syncthreads();
            {
                int b = tid >> 6, row = tid & 63;
                out[(size_t)(bbase + b) * 192 + row] = ps[b * 64 + row] + ps[256 + b * 64 + row];
            }
            // reset accumulators for layer 1
            #pragma unroll
            for (int b = 0; b < NB; b++)
                #pragma unroll
                for (int mi = 0; mi < 2; mi++)
                    #pragma unroll
                    for (int nj = 0; nj < 4; nj++)
                        #pragma unroll
                        for (int q = 0; q < 4; q++) acc[b][mi][nj][q] = 0.0f;
        }

        cp_wait<0>();            // W tile g resident
        __syncthreads();

        const int gl = (g < NT0) ? g : g - NT0;
        const int hid = gl * 2 + (kq >> 1);
        const uint32_t wtile = sb + OFF_W + (uint32_t)(g & 1) * WTILE;

        #pragma unroll
        for (int b = 0; b < NB; b++) {
            // ---- build z tile (64 k x 64 d), fp32 -> bf16 hi/lo, d-major
            const uint32_t zbuf = sb + OFF_Z + (uint32_t)(b & 1) * ZTILE;
            {
                const float* xb = xs + (size_t)b * 2048;
                const float* hrow = (g < NT0) ? (xb + hid * 64)
                                              : (hs + (size_t)b * (64 * HPAD) + hid * HPAD);
                const float xh = hrow[d];
                uint32_t hi[8], lo[8];
                #pragma unroll
                for (int i = 0; i < 8; i++) {
                    float z0 = xh * xb[(m0 + 2 * i) * 64 + d];
                    float z1 = xh * xb[(m0 + 2 * i + 1) * 64 + d];
                    uint32_t p0; asm("cvt.rn.bf16x2.f32 %0, %1, %2;" : "=r"(p0) : "f"(z1), "f"(z0));
                    float r0 = z0 - __uint_as_float(p0 << 16);
                    float r1 = z1 - __uint_as_float(p0 & 0xFFFF0000u);
                    uint32_t p1; asm("cvt.rn.bf16x2.f32 %0, %1, %2;" : "=r"(p1) : "f"(r1), "f"(r0));
                    hi[i] = p0; lo[i] = p1;
                }
                uint32_t a0 = zbuf + (uint32_t)(d * WPITCH + kb * 2);
                sts128(a0,               hi[0], hi[1], hi[2], hi[3]);
                sts128(a0 + 16,          hi[4], hi[5], hi[6], hi[7]);
                sts128(a0 + ZPLANE,      lo[0], lo[1], lo[2], lo[3]);
                sts128(a0 + ZPLANE + 16, lo[4], lo[5], lo[6], lo[7]);
            }
            __syncthreads();

            if (b == 0 && g + 1 < NT_ALL) {   // prefetch next W tile
                const unsigned char* src = g_Wpre + (size_t)(g + 1) * WTILE;
                uint32_t dst = sb + OFF_W + (uint32_t)((g + 1) & 1) * WTILE;
                #pragma unroll
                for (int r = 0; r < 9; r++) {
                    int idx = r * THREADS + tid;
                    if (idx < WTILE / 16)
                        cpa16(dst + (uint32_t)idx * 16, src + (size_t)idx * 16);
                }
                cp_commit();
            }

            // ---- MMA: 4 k-steps, 3 passes
            #pragma unroll
            for (int ks = 0; ks < 4; ks++) {
                const uint32_t kofs = (uint32_t)(ks * 16 + 2 * lc) * 2;
                uint32_t Ah[2][4], Al[2][4], Bh[4][2], Bl[4][2];
                #pragma unroll
                for (int mi = 0; mi < 2; mi++) {
                    uint32_t p = wtile + (uint32_t)((wo * 32 + mi * 16 + lr) * WPITCH) + kofs;
                    Ah[mi][0] = lds32(p);
                    Ah[mi][1] = lds32(p + 8 * WPITCH);
                    Ah[mi][2] = lds32(p + 16);
                    Ah[mi][3] = lds32(p + 8 * WPITCH + 16);
                    uint32_t q = p + WPLANE;
                    Al[mi][0] = lds32(q);
                    Al[mi][1] = lds32(q + 8 * WPITCH);
                    Al[mi][2] = lds32(q + 16);
                    Al[mi][3] = lds32(q + 8 * WPITCH + 16);
                }
                #pragma unroll
                for (int nj = 0; nj < 4; nj++) {
                    uint32_t p = zbuf + (uint32_t)((wn * 32 + nj * 8 + lr) * WPITCH) + kofs;
                    Bh[nj][0] = lds32(p);
                    Bh[nj][1] = lds32(p + 16);
                    Bl[nj][0] = lds32(p + ZPLANE);
                    Bl[nj][1] = lds32(p + ZPLANE + 16);
                }
                #pragma unroll
                for (int mi = 0; mi < 2; mi++)
                    #pragma unroll
                    for (int nj = 0; nj < 4; nj++) mma16816(acc[b][mi][nj], Ah[mi], Bh[nj]);
                #pragma unroll
                for (int mi = 0; mi < 2; mi++)
                    #pragma unroll
                    for (int nj = 0; nj < 4; nj++) mma16816(acc[b][mi][nj], Ah[mi], Bl[nj]);
                #pragma unroll
                for (int mi = 0; mi < 2; mi++)
                    #pragma unroll
                    for (int nj = 0; nj < 4; nj++) mma16816(acc[b][mi][nj], Al[mi], Bh[nj]);
            }
        }
    }

    // ======== layer-1 epilogue: out rows 64..191 ========
    __syncthreads();
    {
        float* ps = (float*)(smem + OFF_Z);   // [wn][b][row<128]
        #pragma unroll
        for (int b = 0; b < NB; b++) {
            #pragma unroll
            for (int mi = 0; mi < 2; mi++) {
                int o = wo * 32 + mi * 16 + lr;
                float bias0 = b1g[o], bias1 = b1g[o + 8];
                float s0 = 0.0f, s1 = 0.0f;
                #pragma unroll
                for (int nj = 0; nj < 4; nj++) {
                    s0 += fmaxf(acc[b][mi][nj][0] + bias0, 0.0f)
                        + fmaxf(acc[b][mi][nj][1] + bias0, 0.0f);
                    s1 += fmaxf(acc[b][mi][nj][2] + bias1, 0.0f)
                        + fmaxf(acc[b][mi][nj][3] + bias1, 0.0f);
                }
                s0 += __shfl_xor_sync(0xffffffffu, s0, 1);
                s0 += __shfl_xor_sync(0xffffffffu, s0, 2);
                s1 += __shfl_xor_sync(0xffffffffu, s1, 1);
                s1 += __shfl_xor_sync(0xffffffffu, s1, 2);
                if (lc == 0) {
                    ps[wn * 512 + b * 128 + o]     = s0;
                    ps[wn * 512 + b * 128 + o + 8] = s1;
                }
            }
        }
        __syncthreads();
        #pragma unroll
        for (int r = 0; r < 2; r++) {
            int idx = r * THREADS + tid;        // 0..511
            int b = idx >> 7, row = idx & 127;
            out[(size_t)(bbase + b) * 192 + 64 + row] = ps[idx] + ps[512 + idx];
        }
    }
}

// ---------------- launch ----------------
extern "C" void kernel_launch(void* const* d_in, const int* in_sizes, int n_in,
                              void* d_out, int out_size) {
    const float* xg = (const float*)d_in[0];   // (2048,32,64)
    const float* W0 = (const float*)d_in[1];   // (128,1024)
    const float* b0 = (const float*)d_in[2];   // (128)
    const float* W1 = (const float*)d_in[3];   // (128,2048)
    const float* b1 = (const float*)d_in[4];   // (128)
    float* out = (float*)d_out;                // (2048,192)

    prep_kernel<<<1536, 256>>>(W0, W1);

    cudaFuncSetAttribute((const void*)cin_mma_kernel,
                         cudaFuncAttributeMaxDynamicSharedMemorySize, SMEM_TOTAL);
    cin_mma_kernel<<<2048 / NB, THREADS, SMEM_TOTAL>>>(xg, b0, b1, out);
}